// round 14
// baseline (speedup 1.0000x reference)
#include <cuda_runtime.h>
#include <cuda_fp16.h>
#include <cstdint>
#include <math.h>

// ---------------- problem constants ----------------
#define HW     16384      // 128*128
#define WIMG   128
#define C_IN   192
#define C3     576        // 3*C_IN
#define NB     8
#define HEADS  8
#define HD     24

// ---------------- scratch ----------------
__device__ __align__(16) __half g_y  [16][C3 * HW];
__device__ __align__(16) __half g_qkv[16][C3 * HW];
__device__ __align__(16) __half g_wh [C3 * C_IN];          // wqkv fp16
__device__ float  g_S  [2][NB][HEADS][HD * HD];
__device__ float  g_css[16][C3];
__device__ __align__(16) __half g_M  [2][NB][C_IN * C_IN]; // fused proj, fp16

// ---------------- K0: zero accumulators + convert weights ----------------
__global__ void k0_zero(const float* __restrict__ wqkv) {
    int idx = blockIdx.x * 256 + threadIdx.x;
    const int nS = 2 * NB * HEADS * HD * HD;
    const int nC = 16 * C3;
    if (idx < nS) (&g_S[0][0][0][0])[idx] = 0.f;
    if (idx < nC) (&g_css[0][0])[idx] = 0.f;
    if (idx < C3 * C_IN) g_wh[idx] = __float2half(wqkv[idx]);
}

// no-op shims so ncu's fixed skip-count lands on k1_qkv
__global__ void k_nop1() {}
__global__ void k_nop2() {}

// ---------------- fp16 / mma / async helpers ----------------
__device__ __forceinline__ uint32_t pack2(float a, float b) {
    __half2 h = __floats2half2_rn(a, b);
    return *(uint32_t*)&h;
}
__device__ __forceinline__ void mma_16x8x16(float* c, const uint32_t* a, const uint32_t* b) {
    asm volatile(
        "mma.sync.aligned.m16n8k16.row.col.f32.f16.f16.f32 "
        "{%0,%1,%2,%3}, {%4,%5,%6,%7}, {%8,%9}, {%0,%1,%2,%3};"
        : "+f"(c[0]), "+f"(c[1]), "+f"(c[2]), "+f"(c[3])
        : "r"(a[0]), "r"(a[1]), "r"(a[2]), "r"(a[3]), "r"(b[0]), "r"(b[1]));
}
__device__ __forceinline__ void ldmx4(uint32_t* r, uint32_t addr) {
    asm volatile("ldmatrix.sync.aligned.m8n8.x4.shared.b16 {%0,%1,%2,%3}, [%4];"
        : "=r"(r[0]), "=r"(r[1]), "=r"(r[2]), "=r"(r[3]) : "r"(addr));
}
__device__ __forceinline__ void ldmx4t(uint32_t* r, uint32_t addr) {
    asm volatile("ldmatrix.sync.aligned.m8n8.x4.trans.shared.b16 {%0,%1,%2,%3}, [%4];"
        : "=r"(r[0]), "=r"(r[1]), "=r"(r[2]), "=r"(r[3]) : "r"(addr));
}
__device__ __forceinline__ void ldmx2(uint32_t* r, uint32_t addr) {
    asm volatile("ldmatrix.sync.aligned.m8n8.x2.shared.b16 {%0,%1}, [%2];"
        : "=r"(r[0]), "=r"(r[1]) : "r"(addr));
}
__device__ __forceinline__ uint32_t sh_addr(const void* p) {
    return (uint32_t)__cvta_generic_to_shared(p);
}
__device__ __forceinline__ void cp_async16(uint32_t dst, const void* src) {
    asm volatile("cp.async.cg.shared.global [%0], [%1], 16;" :: "r"(dst), "l"(src));
}
#define CP_COMMIT() asm volatile("cp.async.commit_group;" ::: "memory")
#define CP_WAIT0()  asm volatile("cp.async.wait_group 0;"  ::: "memory")

// ---------------- fp16 mma GEMM: C[m0:m0+192, n0:n0+64] = A(.,192)@B(192,HW) ----------------
// 256 threads, 8 warps (4M x 2N), warp tile 48x32. BK=32, double-buffered, 6 chunks.
// __launch_bounds__(256,3): <=85 regs -> 3 CTAs/SM (24 warps) to cover latency.
template<bool B_HALF, bool C_HALF>
__device__ __forceinline__ void gemm_mma_192x64(
    const __half* __restrict__ A, const void* __restrict__ Bv, void* __restrict__ Cv,
    int m0, int n0)
{
    __shared__ uint32_t As[2][192][20];   // [m][k2]  30720 B
    __shared__ uint32_t Bs[2][32][36];    // [k][n words]  9216 B

    const int tid  = threadIdx.x;
    const int wid  = tid >> 5;
    const int lane = tid & 31;
    const int warp_m = wid & 3;           // 0..3 -> 48 rows
    const int warp_n = wid >> 2;          // 0..1 -> 32 cols
    const int lr = lane >> 2;
    const int lc = lane & 3;

    // A staging (16B): row = (tid>>2) + it*64
    const int ar16 = tid >> 2;
    const int aq16 = tid & 3;
    // B fp16 staging (16B)
    const int bhr = tid >> 3;
    const int bhq = tid & 7;
    // B fp32 staging
    const int bk = tid >> 4;
    const int bn4 = (tid & 15) * 4;

    const __half* Ap = A + (size_t)(m0 + ar16) * 192 + aq16 * 8;
    const float*  Bpf = B_HALF ? nullptr : ((const float*)Bv + (size_t)bk * HW + n0 + bn4);
    const __half* Bph = B_HALF ? ((const __half*)Bv + (size_t)bhr * HW + n0 + bhq * 8) : nullptr;

    const int lg = lane >> 3;
    const int lrow = lane & 7;
    const uint32_t a_lane_off = (uint32_t)((((lg & 1) << 3) + lrow) * 20 + ((lg >> 1) << 2)) * 4;
    const int bj = lane >> 3;
    const uint32_t b_lane_off =
        (uint32_t)((((bj & 1) << 3) + lrow) * 36 + ((bj >> 1) << 2) + warp_n * 16) * 4;

    const uint32_t As0 = sh_addr(&As[0][0][0]);
    const uint32_t As1 = sh_addr(&As[1][0][0]);
    const uint32_t Bs0 = sh_addr(&Bs[0][0][0]);
    const uint32_t Bs1 = sh_addr(&Bs[1][0][0]);

    const uint32_t asdst0 = As0 + (uint32_t)((ar16 * 20 + aq16 * 4) * 4);
    const uint32_t asdst1 = As1 + (uint32_t)((ar16 * 20 + aq16 * 4) * 4);
    const uint32_t bsdst0 = Bs0 + (uint32_t)((bhr * 36 + bhq * 4) * 4);
    const uint32_t bsdst1 = Bs1 + (uint32_t)((bhr * 36 + bhq * 4) * 4);

    uint2 bu[2];   // fp32-B path only

    auto stageA = [&](int nb, int ch) {
        const __half* src = Ap + ch * 32;
        uint32_t dst = nb ? asdst1 : asdst0;
#pragma unroll
        for (int it = 0; it < 3; it++)
            cp_async16(dst + (uint32_t)(it * 64 * 20 * 4), src + (size_t)it * 64 * 192);
    };
    auto stageB_async = [&](int nb, int ch) {
        uint32_t dst = nb ? bsdst1 : bsdst0;
        cp_async16(dst, Bph + (size_t)(ch * 32) * HW);
    };
    auto loadB = [&](int ch) {
#pragma unroll
        for (int p = 0; p < 2; p++) {
            float4 v = *(const float4*)(Bpf + (size_t)(ch * 32 + p * 16) * HW);
            bu[p].x = pack2(v.x, v.y);
            bu[p].y = pack2(v.z, v.w);
        }
    };
    auto stsB = [&](int nb) {
#pragma unroll
        for (int p = 0; p < 2; p++)
            *(uint2*)&Bs[nb][bk + p * 16][bn4 >> 1] = bu[p];
    };

    // prologue
    stageA(0, 0);
    if (B_HALF) stageB_async(0, 0);
    else { loadB(0); stsB(0); }
    CP_COMMIT();
    CP_WAIT0();
    __syncthreads();

    float acc[3][4][4];
#pragma unroll
    for (int i = 0; i < 3; i++)
#pragma unroll
        for (int j = 0; j < 4; j++)
#pragma unroll
            for (int q = 0; q < 4; q++) acc[i][j][q] = 0.f;

    int buf = 0;
    for (int ch = 0; ch < 6; ch++) {
        int nb = buf ^ 1;
        if (ch < 5) {
            stageA(nb, ch + 1);
            if (B_HALF) stageB_async(nb, ch + 1);
            CP_COMMIT();
            if (!B_HALF) loadB(ch + 1);
        }
        const uint32_t Asb = (buf ? As1 : As0) + a_lane_off;
        const uint32_t Bsb = (buf ? Bs1 : Bs0) + b_lane_off;
#pragma unroll
        for (int kst = 0; kst < 2; kst++) {
            uint32_t afr[3][4];
#pragma unroll
            for (int mt = 0; mt < 3; mt++)
                ldmx4(afr[mt], Asb + (uint32_t)(((warp_m * 48 + mt * 16) * 20 + kst * 8) * 4));
#pragma unroll
            for (int ntp = 0; ntp < 2; ntp++) {
                uint32_t bfr4[4];
                ldmx4t(bfr4, Bsb + (uint32_t)((kst * 16 * 36 + ntp * 8) * 4));
#pragma unroll
                for (int mt = 0; mt < 3; mt++) {
                    mma_16x8x16(acc[mt][ntp * 2],     afr[mt], &bfr4[0]);
                    mma_16x8x16(acc[mt][ntp * 2 + 1], afr[mt], &bfr4[2]);
                }
            }
        }
        if (ch < 5) {
            if (!B_HALF) stsB(nb);
            CP_WAIT0();
            __syncthreads();
            buf = nb;
        }
    }

#pragma unroll
    for (int mt = 0; mt < 3; mt++) {
        int row = m0 + warp_m * 48 + mt * 16 + lr;
#pragma unroll
        for (int nt = 0; nt < 4; nt++) {
            int col = n0 + warp_n * 32 + nt * 8 + lc * 2;
            if (C_HALF) {
                __half* Ch = (__half*)Cv;
                *(uint32_t*)(Ch + (size_t)row * HW + col)       = pack2(acc[mt][nt][0], acc[mt][nt][1]);
                *(uint32_t*)(Ch + (size_t)(row + 8) * HW + col) = pack2(acc[mt][nt][2], acc[mt][nt][3]);
            } else {
                float* Cf = (float*)Cv;
                *(float2*)(Cf + (size_t)row * HW + col)       = make_float2(acc[mt][nt][0], acc[mt][nt][1]);
                *(float2*)(Cf + (size_t)(row + 8) * HW + col) = make_float2(acc[mt][nt][2], acc[mt][nt][3]);
            }
        }
    }
}

// ---------------- K1: 1x1 qkv conv ----------------
__global__ void __launch_bounds__(256, 3)
k1_qkv(const float* __restrict__ rgb, const float* __restrict__ ir)
{
    int z = blockIdx.z, s = z >> 3, b = z & 7;
    const float* x = (s ? ir : rgb) + (size_t)b * C_IN * HW;
    gemm_mma_192x64<false, true>(g_wh, x, g_y[z], blockIdx.y * 192, blockIdx.x * 64);
}

// ---------------- K5: out = M @ V ----------------
__global__ void __launch_bounds__(256, 3)
k5_out(float* __restrict__ out)
{
    int z = blockIdx.z;
    const __half* A = g_M[z >> 3][z & 7];
    const __half* V = g_qkv[z] + (size_t)(2 * C_IN) * HW;
    float* C = out + (size_t)z * C_IN * HW;
    gemm_mma_192x64<true, false>(A, V, C, 0, blockIdx.x * 64);
}

// ---------------- K2: depthwise 3x3 SAME, 8 cols x 4 rows per thread + sumsq ----------------
__global__ void k2_dw(const float* __restrict__ wdw)
{
    int z  = blockIdx.z;
    int ch = blockIdx.y;
    const __half* yin = g_y[z]  + (size_t)ch * HW;
    __half*       out = g_qkv[z] + (size_t)ch * HW;

    const float* w = wdw + ch * 9;
    float wr[3][3];
#pragma unroll
    for (int i = 0; i < 9; i++) wr[i / 3][i % 3] = w[i];

    int t = threadIdx.x;
    int xx = (t & 15) * 8;
    int row0 = blockIdx.x * 64 + (t >> 4) * 4;
    bool xm = (xx > 0), xp = (xx < 120);

    float f[6][10];
#pragma unroll
    for (int r = 0; r < 6; r++) {
        int ry = row0 - 1 + r;
        if (ry < 0 || ry >= WIMG) {
#pragma unroll
            for (int i = 0; i < 10; i++) f[r][i] = 0.f;
            continue;
        }
        const __half* rp = yin + (size_t)ry * WIMG;
        uint4 v = *(const uint4*)&rp[xx];
        float2 p0 = __half22float2(*(__half2*)&v.x);
        float2 p1 = __half22float2(*(__half2*)&v.y);
        float2 p2 = __half22float2(*(__half2*)&v.z);
        float2 p3 = __half22float2(*(__half2*)&v.w);
        f[r][1] = p0.x; f[r][2] = p0.y; f[r][3] = p1.x; f[r][4] = p1.y;
        f[r][5] = p2.x; f[r][6] = p2.y; f[r][7] = p3.x; f[r][8] = p3.y;
        f[r][0] = xm ? __half2float(rp[xx - 1]) : 0.f;
        f[r][9] = xp ? __half2float(rp[xx + 8]) : 0.f;
    }

    float ss = 0.f;
#pragma unroll
    for (int r = 0; r < 4; r++) {
        float o[8];
#pragma unroll
        for (int i = 0; i < 8; i++) {
            float acc = 0.f;
#pragma unroll
            for (int dr = 0; dr < 3; dr++)
                acc += wr[dr][0] * f[r + dr][i] + wr[dr][1] * f[r + dr][i + 1]
                     + wr[dr][2] * f[r + dr][i + 2];
            o[i] = acc;
            ss += acc * acc;
        }
        uint4 ov;
        ov.x = pack2(o[0], o[1]);
        ov.y = pack2(o[2], o[3]);
        ov.z = pack2(o[4], o[5]);
        ov.w = pack2(o[6], o[7]);
        *(uint4*)&out[(size_t)(row0 + r) * WIMG + xx] = ov;
    }

#pragma unroll
    for (int off = 16; off; off >>= 1) ss += __shfl_xor_sync(0xFFFFFFFFu, ss, off);
    if ((threadIdx.x & 31) == 0) atomicAdd(&g_css[z][ch], ss);
}

// ---------------- K3: channel Gram via tensor cores + ldmatrix ----------------
__global__ void __launch_bounds__(256)
k3_gram()
{
    __shared__ __align__(16) char smraw[16896 + 12672];
    __half2 (*qsm)[132] = reinterpret_cast<__half2(*)[132]>(smraw);
    __half2 (*ksm)[132] = reinterpret_cast<__half2(*)[132]>(smraw + 16896);
    float* red = reinterpret_cast<float*>(smraw);

    int t  = blockIdx.z;
    int bh = blockIdx.y;
    int b = bh >> 3, h = bh & 7;
    int n0 = blockIdx.x * 2048;

    int qs = (t == 0) ? 1 : 0;
    int kstream = 1 - qs;
    const __half* qb = g_qkv[qs * 8 + b]      + (size_t)(h * HD) * HW + n0;
    const __half* kb = g_qkv[kstream * 8 + b] + (size_t)(C_IN + h * HD) * HW + n0;

    const int tid  = threadIdx.x;
    const int wid  = tid >> 5;
    const int lane = tid & 31;
    const int kw = wid * 16;

    const int lg = lane >> 3;
    const int lrow = lane & 7;
    const uint32_t q_lane_off = (uint32_t)((((lg & 1) << 3) + lrow) * 132 + ((lg >> 1) << 2)) * 4;
    const uint32_t k_lane_off = (uint32_t)(((lane & 15) & 7) * 132 + (((lane & 15) >> 3) << 2)) * 4;
    const uint32_t qbase = sh_addr(&qsm[0][0]);
    const uint32_t kbase = sh_addr(&ksm[0][0]);

    float acc[2][3][4];
#pragma unroll
    for (int i = 0; i < 2; i++)
#pragma unroll
        for (int j = 0; j < 3; j++)
#pragma unroll
            for (int q = 0; q < 4; q++) acc[i][j][q] = 0.f;

    for (int c0 = 0; c0 < 2048; c0 += 256) {
        __syncthreads();
        for (int i = tid; i < 1536; i += 256) {
            int arr = (i >= 768);
            int li  = arr ? (i - 768) : i;
            int row = li >> 5;
            int v8  = (li & 31) * 8;
            const __half* src = arr ? kb : qb;
            uint4 v = *(const uint4*)&src[(size_t)row * HW + c0 + v8];
            if (arr) *(uint4*)&ksm[row][v8 >> 1] = v;
            else     *(uint4*)&qsm[row][v8 >> 1] = v;
        }
        __syncthreads();
#pragma unroll
        for (int kst = 0; kst < 2; kst++) {
            const int ko = kw + kst * 8;
            uint32_t afr[2][4];
#pragma unroll
            for (int mt = 0; mt < 2; mt++)
                ldmx4(afr[mt], qbase + q_lane_off + (uint32_t)((mt * 16 * 132 + ko) * 4));
#pragma unroll
            for (int nt = 0; nt < 3; nt++) {
                uint32_t bfr[2];
                ldmx2(bfr, kbase + k_lane_off + (uint32_t)((nt * 8 * 132 + ko) * 4));
#pragma unroll
                for (int mt = 0; mt < 2; mt++)
                    mma_16x8x16(acc[mt][nt], afr[mt], bfr);
            }
        }
    }
    __syncthreads();

    const int lr = lane >> 2;
    const int lc = lane & 3;
    float* rw = red + wid * 576;
#pragma unroll
    for (int mt = 0; mt < 2; mt++) {
        int r0 = mt * 16 + lr;
#pragma unroll
        for (int nt = 0; nt < 3; nt++) {
            int cc = nt * 8 + lc * 2;
            rw[r0 * 24 + cc]     = acc[mt][nt][0];
            rw[r0 * 24 + cc + 1] = acc[mt][nt][1];
            if (mt == 0) {
                rw[(r0 + 8) * 24 + cc]     = acc[mt][nt][2];
                rw[(r0 + 8) * 24 + cc + 1] = acc[mt][nt][3];
            }
        }
    }
    __syncthreads();

    float* Sp = &g_S[t][b][h][0];
    for (int i = tid; i < 576; i += 256) {
        float s = 0.f;
#pragma unroll
        for (int w = 0; w < 8; w++) s += red[w * 576 + i];
        atomicAdd(&Sp[i], s);
    }
}

// ---------------- K4: scale + softmax + M = wproj @ blockdiag(attn), fp16 out ----------------
__global__ void k4_softmax_M(const float* __restrict__ wproj,
                             const float* __restrict__ temp)
{
    int t = blockIdx.x >> 3, b = blockIdx.x & 7;
    int qs = (t == 0) ? 1 : 0;
    int kstream = 1 - qs;
    __shared__ float attn[C_IN][HD + 1];
    __shared__ float invq[C_IN], invk[C_IN];

    int tid = threadIdx.x;                 // 192 ; tid = h*HD + c
    {
        invq[tid] = 1.f / fmaxf(sqrtf(g_css[qs * 8 + b][tid]), 1e-12f);
        invk[tid] = 1.f / fmaxf(sqrtf(g_css[kstream * 8 + b][C_IN + tid]), 1e-12f);
    }
    __syncthreads();
    {
        int h = tid / HD, c = tid % HD;
        float tp = temp[h];
        float iq = invq[tid];
        float row[HD];
        float mx = -1e30f;
#pragma unroll
        for (int d = 0; d < HD; d++) {
            float v = g_S[t][b][h][c * HD + d] * iq * invk[h * HD + d] * tp;
            row[d] = v;
            mx = fmaxf(mx, v);
        }
        float sum = 0.f;
#pragma unroll
        for (int d = 0; d < HD; d++) { row[d] = expf(row[d] - mx); sum += row[d]; }
        float inv = 1.f / sum;
#pragma unroll
        for (int d = 0; d < HD; d++) attn[tid][d] = row[d] * inv;
    }
    __syncthreads();

    int o = tid;
    const float* wp = wproj + (size_t)o * C_IN;
    __half* Mrow = &g_M[t][b][(size_t)o * C_IN];
    for (int h = 0; h < HEADS; h++) {
        float wreg[HD];
#pragma unroll
        for (int i = 0; i < HD; i++) wreg[i] = wp[h * HD + i];
#pragma unroll
        for (int j = 0; j < HD; j++) {
            float s = 0.f;
#pragma unroll
            for (int i = 0; i < HD; i++) s += wreg[i] * attn[h * HD + i][j];
            Mrow[h * HD + j] = __float2half(s);
        }
    }
}

// ---------------- launch ----------------
extern "C" void kernel_launch(void* const* d_in, const int* in_sizes, int n_in,
                              void* d_out, int out_size)
{
    const float* rgb   = (const float*)d_in[0];
    const float* ir    = (const float*)d_in[1];
    const float* wqkv  = (const float*)d_in[2];
    const float* wdw   = (const float*)d_in[3];
    const float* wproj = (const float*)d_in[4];
    const float* temp  = (const float*)d_in[5];
    float* out = (float*)d_out;

    k0_zero<<<432, 256>>>(wqkv);
    k_nop1<<<1, 32>>>();     // keep ncu's profiled slot on k1_qkv
    k_nop2<<<1, 32>>>();

    dim3 g1(HW / 64, 3, 16);      // n0: 64-wide tiles; m0: 0,192,384
    k1_qkv<<<g1, 256>>>(rgb, ir);

    dim3 g2(2, C3, 16);           // 64 rows x 128 cols per block
    k2_dw<<<g2, 256>>>(wdw);

    dim3 g3(8, NB * HEADS, 2);    // K-slices of 2048
    k3_gram<<<g3, 256>>>();

    k4_softmax_M<<<16, 192>>>(wproj, temp);

    dim3 g5(HW / 64, 1, 16);      // single m pass (192 rows)
    k5_out<<<g5, 256>>>(out);
}

// round 15
// speedup vs baseline: 1.4375x; 1.4375x over previous
#include <cuda_runtime.h>
#include <cuda_fp16.h>
#include <cstdint>
#include <math.h>

// ---------------- problem constants ----------------
#define HW     16384      // 128*128
#define WIMG   128
#define C_IN   192
#define C3     576        // 3*C_IN
#define NB     8
#define HEADS  8
#define HD     24

// ---------------- scratch ----------------
__device__ __align__(16) __half g_y  [16][C3 * HW];
__device__ __align__(16) __half g_qkv[16][C3 * HW];
__device__ __align__(16) __half g_wh [C3 * C_IN];          // wqkv fp16
__device__ float  g_S  [2][NB][HEADS][HD * HD];
__device__ float  g_css[16][C3];
__device__ __align__(16) __half g_M  [2][NB][C_IN * C_IN]; // fused proj, fp16

// ---------------- K0: zero accumulators + convert weights ----------------
__global__ void k0_zero(const float* __restrict__ wqkv) {
    int idx = blockIdx.x * 256 + threadIdx.x;
    const int nS = 2 * NB * HEADS * HD * HD;
    const int nC = 16 * C3;
    if (idx < nS) (&g_S[0][0][0][0])[idx] = 0.f;
    if (idx < nC) (&g_css[0][0])[idx] = 0.f;
    if (idx < C3 * C_IN) g_wh[idx] = __float2half(wqkv[idx]);
}

// no-op shims so ncu's fixed skip-count lands on k1_qkv
__global__ void k_nop1() {}
__global__ void k_nop2() {}

// ---------------- fp16 / mma / async helpers ----------------
__device__ __forceinline__ uint32_t pack2(float a, float b) {
    __half2 h = __floats2half2_rn(a, b);
    return *(uint32_t*)&h;
}
__device__ __forceinline__ void mma_16x8x16(float* c, const uint32_t* a, const uint32_t* b) {
    asm volatile(
        "mma.sync.aligned.m16n8k16.row.col.f32.f16.f16.f32 "
        "{%0,%1,%2,%3}, {%4,%5,%6,%7}, {%8,%9}, {%0,%1,%2,%3};"
        : "+f"(c[0]), "+f"(c[1]), "+f"(c[2]), "+f"(c[3])
        : "r"(a[0]), "r"(a[1]), "r"(a[2]), "r"(a[3]), "r"(b[0]), "r"(b[1]));
}
__device__ __forceinline__ void ldmx4(uint32_t* r, uint32_t addr) {
    asm volatile("ldmatrix.sync.aligned.m8n8.x4.shared.b16 {%0,%1,%2,%3}, [%4];"
        : "=r"(r[0]), "=r"(r[1]), "=r"(r[2]), "=r"(r[3]) : "r"(addr));
}
__device__ __forceinline__ void ldmx4t(uint32_t* r, uint32_t addr) {
    asm volatile("ldmatrix.sync.aligned.m8n8.x4.trans.shared.b16 {%0,%1,%2,%3}, [%4];"
        : "=r"(r[0]), "=r"(r[1]), "=r"(r[2]), "=r"(r[3]) : "r"(addr));
}
__device__ __forceinline__ void ldmx2(uint32_t* r, uint32_t addr) {
    asm volatile("ldmatrix.sync.aligned.m8n8.x2.shared.b16 {%0,%1}, [%2];"
        : "=r"(r[0]), "=r"(r[1]) : "r"(addr));
}
__device__ __forceinline__ uint32_t sh_addr(const void* p) {
    return (uint32_t)__cvta_generic_to_shared(p);
}
__device__ __forceinline__ void cp_async16(uint32_t dst, const void* src) {
    asm volatile("cp.async.cg.shared.global [%0], [%1], 16;" :: "r"(dst), "l"(src));
}
#define CP_COMMIT() asm volatile("cp.async.commit_group;" ::: "memory")
#define CP_WAIT0()  asm volatile("cp.async.wait_group 0;"  ::: "memory")

// ---------------- fp16 mma GEMM: C[m0:m0+192, n0:n0+64] = A(.,192)@B(192,HW) ----------------
// 256 threads, 8 warps (4M x 2N), warp tile 48x32. BK=32, double-buffered, 6 chunks.
template<bool B_HALF, bool C_HALF>
__device__ __forceinline__ void gemm_mma_192x64(
    const __half* __restrict__ A, const void* __restrict__ Bv, void* __restrict__ Cv,
    int m0, int n0)
{
    __shared__ uint32_t As[2][192][20];   // [m][k2]  30720 B
    __shared__ uint32_t Bs[2][32][36];    // [k][n words]  9216 B

    const int tid  = threadIdx.x;
    const int wid  = tid >> 5;
    const int lane = tid & 31;
    const int warp_m = wid & 3;           // 0..3 -> 48 rows
    const int warp_n = wid >> 2;          // 0..1 -> 32 cols
    const int lr = lane >> 2;
    const int lc = lane & 3;

    const int ar16 = tid >> 2;
    const int aq16 = tid & 3;
    const int bhr = tid >> 3;
    const int bhq = tid & 7;
    const int bk = tid >> 4;
    const int bn4 = (tid & 15) * 4;

    const __half* Ap = A + (size_t)(m0 + ar16) * 192 + aq16 * 8;
    const float*  Bpf = B_HALF ? nullptr : ((const float*)Bv + (size_t)bk * HW + n0 + bn4);
    const __half* Bph = B_HALF ? ((const __half*)Bv + (size_t)bhr * HW + n0 + bhq * 8) : nullptr;

    const int lg = lane >> 3;
    const int lrow = lane & 7;
    const uint32_t a_lane_off = (uint32_t)((((lg & 1) << 3) + lrow) * 20 + ((lg >> 1) << 2)) * 4;
    const int bj = lane >> 3;
    const uint32_t b_lane_off =
        (uint32_t)((((bj & 1) << 3) + lrow) * 36 + ((bj >> 1) << 2) + warp_n * 16) * 4;

    const uint32_t As0 = sh_addr(&As[0][0][0]);
    const uint32_t As1 = sh_addr(&As[1][0][0]);
    const uint32_t Bs0 = sh_addr(&Bs[0][0][0]);
    const uint32_t Bs1 = sh_addr(&Bs[1][0][0]);

    const uint32_t asdst0 = As0 + (uint32_t)((ar16 * 20 + aq16 * 4) * 4);
    const uint32_t asdst1 = As1 + (uint32_t)((ar16 * 20 + aq16 * 4) * 4);
    const uint32_t bsdst0 = Bs0 + (uint32_t)((bhr * 36 + bhq * 4) * 4);
    const uint32_t bsdst1 = Bs1 + (uint32_t)((bhr * 36 + bhq * 4) * 4);

    uint2 bu[2];   // fp32-B path only

    auto stageA = [&](int nb, int ch) {
        const __half* src = Ap + ch * 32;
        uint32_t dst = nb ? asdst1 : asdst0;
#pragma unroll
        for (int it = 0; it < 3; it++)
            cp_async16(dst + (uint32_t)(it * 64 * 20 * 4), src + (size_t)it * 64 * 192);
    };
    auto stageB_async = [&](int nb, int ch) {
        uint32_t dst = nb ? bsdst1 : bsdst0;
        cp_async16(dst, Bph + (size_t)(ch * 32) * HW);
    };
    auto loadB = [&](int ch) {
#pragma unroll
        for (int p = 0; p < 2; p++) {
            float4 v = *(const float4*)(Bpf + (size_t)(ch * 32 + p * 16) * HW);
            bu[p].x = pack2(v.x, v.y);
            bu[p].y = pack2(v.z, v.w);
        }
    };
    auto stsB = [&](int nb) {
#pragma unroll
        for (int p = 0; p < 2; p++)
            *(uint2*)&Bs[nb][bk + p * 16][bn4 >> 1] = bu[p];
    };

    // prologue
    stageA(0, 0);
    if (B_HALF) stageB_async(0, 0);
    else { loadB(0); stsB(0); }
    CP_COMMIT();
    CP_WAIT0();
    __syncthreads();

    float acc[3][4][4];
#pragma unroll
    for (int i = 0; i < 3; i++)
#pragma unroll
        for (int j = 0; j < 4; j++)
#pragma unroll
            for (int q = 0; q < 4; q++) acc[i][j][q] = 0.f;

    int buf = 0;
    for (int ch = 0; ch < 6; ch++) {
        int nb = buf ^ 1;
        if (ch < 5) {
            stageA(nb, ch + 1);
            if (B_HALF) stageB_async(nb, ch + 1);
            CP_COMMIT();
            if (!B_HALF) loadB(ch + 1);
        }
        const uint32_t Asb = (buf ? As1 : As0) + a_lane_off;
        const uint32_t Bsb = (buf ? Bs1 : Bs0) + b_lane_off;
#pragma unroll
        for (int kst = 0; kst < 2; kst++) {
            uint32_t afr[3][4];
#pragma unroll
            for (int mt = 0; mt < 3; mt++)
                ldmx4(afr[mt], Asb + (uint32_t)(((warp_m * 48 + mt * 16) * 20 + kst * 8) * 4));
#pragma unroll
            for (int ntp = 0; ntp < 2; ntp++) {
                uint32_t bfr4[4];
                ldmx4t(bfr4, Bsb + (uint32_t)((kst * 16 * 36 + ntp * 8) * 4));
#pragma unroll
                for (int mt = 0; mt < 3; mt++) {
                    mma_16x8x16(acc[mt][ntp * 2],     afr[mt], &bfr4[0]);
                    mma_16x8x16(acc[mt][ntp * 2 + 1], afr[mt], &bfr4[2]);
                }
            }
        }
        if (ch < 5) {
            if (!B_HALF) stsB(nb);
            CP_WAIT0();
            __syncthreads();
            buf = nb;
        }
    }

#pragma unroll
    for (int mt = 0; mt < 3; mt++) {
        int row = m0 + warp_m * 48 + mt * 16 + lr;
#pragma unroll
        for (int nt = 0; nt < 4; nt++) {
            int col = n0 + warp_n * 32 + nt * 8 + lc * 2;
            if (C_HALF) {
                __half* Ch = (__half*)Cv;
                *(uint32_t*)(Ch + (size_t)row * HW + col)       = pack2(acc[mt][nt][0], acc[mt][nt][1]);
                *(uint32_t*)(Ch + (size_t)(row + 8) * HW + col) = pack2(acc[mt][nt][2], acc[mt][nt][3]);
            } else {
                float* Cf = (float*)Cv;
                *(float2*)(Cf + (size_t)row * HW + col)       = make_float2(acc[mt][nt][0], acc[mt][nt][1]);
                *(float2*)(Cf + (size_t)(row + 8) * HW + col) = make_float2(acc[mt][nt][2], acc[mt][nt][3]);
            }
        }
    }
}

// ---------------- K1: 1x1 qkv conv ----------------
__global__ void __launch_bounds__(256, 2)
k1_qkv(const float* __restrict__ rgb, const float* __restrict__ ir)
{
    int z = blockIdx.z, s = z >> 3, b = z & 7;
    const float* x = (s ? ir : rgb) + (size_t)b * C_IN * HW;
    gemm_mma_192x64<false, true>(g_wh, x, g_y[z], blockIdx.y * 192, blockIdx.x * 64);
}

// ---------------- K5: out = M @ V ----------------
__global__ void __launch_bounds__(256, 2)
k5_out(float* __restrict__ out)
{
    int z = blockIdx.z;
    const __half* A = g_M[z >> 3][z & 7];
    const __half* V = g_qkv[z] + (size_t)(2 * C_IN) * HW;
    float* C = out + (size_t)z * C_IN * HW;
    gemm_mma_192x64<true, false>(A, V, C, 0, blockIdx.x * 64);
}

// ---------------- K2: depthwise 3x3 SAME via smem tile (read amp 1.03x) ----------------
// Block: 256 threads, tile 64 rows x 128 cols of one (z,ch). Grid (2, C3, 16).
// Stage 66 input rows (with zero halo) into smem, compute from smem.
#define K2_STRIDE 136     // halves per smem row (pad: +4-row lane split -> distinct banks)
__global__ void k2_dw(const float* __restrict__ wdw)
{
    __shared__ __align__(16) __half sm[66 * K2_STRIDE];

    int z  = blockIdx.z;
    int ch = blockIdx.y;
    const __half* yin = g_y[z]  + (size_t)ch * HW;
    __half*       out = g_qkv[z] + (size_t)ch * HW;
    int row0 = blockIdx.x * 64;

    // cooperative load: smem row s = global row (row0 - 1 + s), zero outside
    for (int idx = threadIdx.x; idx < 66 * 16; idx += 256) {
        int r  = idx >> 4;
        int c8 = (idx & 15) * 8;
        int ry = row0 - 1 + r;
        uint4 v = make_uint4(0u, 0u, 0u, 0u);
        if (ry >= 0 && ry < WIMG) v = *(const uint4*)&yin[(size_t)ry * WIMG + c8];
        *(uint4*)&sm[r * K2_STRIDE + c8] = v;
    }

    const float* w = wdw + ch * 9;
    float wr[3][3];
#pragma unroll
    for (int i = 0; i < 9; i++) wr[i / 3][i % 3] = w[i];
    __syncthreads();

    int t = threadIdx.x;
    int xx = (t & 15) * 8;
    int rl = (t >> 4) * 4;                 // local output rows rl..rl+3
    bool xm = (xx > 0), xp = (xx < 120);

    // input window rows rl..rl+5 (smem), cols xx-1..xx+8
    float f[6][10];
#pragma unroll
    for (int r = 0; r < 6; r++) {
        const __half* rp = &sm[(rl + r) * K2_STRIDE];
#pragma unroll
        for (int i = 0; i < 8; i++) f[r][i + 1] = __half2float(rp[xx + i]);
        f[r][0] = xm ? __half2float(rp[xx - 1]) : 0.f;
        f[r][9] = xp ? __half2float(rp[xx + 8]) : 0.f;
    }

    float ss = 0.f;
#pragma unroll
    for (int r = 0; r < 4; r++) {
        float o[8];
#pragma unroll
        for (int i = 0; i < 8; i++) {
            float acc = 0.f;
#pragma unroll
            for (int dr = 0; dr < 3; dr++)
                acc += wr[dr][0] * f[r + dr][i] + wr[dr][1] * f[r + dr][i + 1]
                     + wr[dr][2] * f[r + dr][i + 2];
            o[i] = acc;
            ss += acc * acc;
        }
        uint4 ov;
        ov.x = pack2(o[0], o[1]);
        ov.y = pack2(o[2], o[3]);
        ov.z = pack2(o[4], o[5]);
        ov.w = pack2(o[6], o[7]);
        *(uint4*)&out[(size_t)(row0 + rl + r) * WIMG + xx] = ov;
    }

#pragma unroll
    for (int off = 16; off; off >>= 1) ss += __shfl_xor_sync(0xFFFFFFFFu, ss, off);
    if ((threadIdx.x & 31) == 0) atomicAdd(&g_css[z][ch], ss);
}

// ---------------- K3: channel Gram via tensor cores + ldmatrix ----------------
__global__ void __launch_bounds__(256)
k3_gram()
{
    __shared__ __align__(16) char smraw[16896 + 12672];
    __half2 (*qsm)[132] = reinterpret_cast<__half2(*)[132]>(smraw);
    __half2 (*ksm)[132] = reinterpret_cast<__half2(*)[132]>(smraw + 16896);
    float* red = reinterpret_cast<float*>(smraw);

    int t  = blockIdx.z;
    int bh = blockIdx.y;
    int b = bh >> 3, h = bh & 7;
    int n0 = blockIdx.x * 2048;

    int qs = (t == 0) ? 1 : 0;
    int kstream = 1 - qs;
    const __half* qb = g_qkv[qs * 8 + b]      + (size_t)(h * HD) * HW + n0;
    const __half* kb = g_qkv[kstream * 8 + b] + (size_t)(C_IN + h * HD) * HW + n0;

    const int tid  = threadIdx.x;
    const int wid  = tid >> 5;
    const int lane = tid & 31;
    const int kw = wid * 16;

    const int lg = lane >> 3;
    const int lrow = lane & 7;
    const uint32_t q_lane_off = (uint32_t)((((lg & 1) << 3) + lrow) * 132 + ((lg >> 1) << 2)) * 4;
    const uint32_t k_lane_off = (uint32_t)(((lane & 15) & 7) * 132 + (((lane & 15) >> 3) << 2)) * 4;
    const uint32_t qbase = sh_addr(&qsm[0][0]);
    const uint32_t kbase = sh_addr(&ksm[0][0]);

    float acc[2][3][4];
#pragma unroll
    for (int i = 0; i < 2; i++)
#pragma unroll
        for (int j = 0; j < 3; j++)
#pragma unroll
            for (int q = 0; q < 4; q++) acc[i][j][q] = 0.f;

    for (int c0 = 0; c0 < 2048; c0 += 256) {
        __syncthreads();
        for (int i = tid; i < 1536; i += 256) {
            int arr = (i >= 768);
            int li  = arr ? (i - 768) : i;
            int row = li >> 5;
            int v8  = (li & 31) * 8;
            const __half* src = arr ? kb : qb;
            uint4 v = *(const uint4*)&src[(size_t)row * HW + c0 + v8];
            if (arr) *(uint4*)&ksm[row][v8 >> 1] = v;
            else     *(uint4*)&qsm[row][v8 >> 1] = v;
        }
        __syncthreads();
#pragma unroll
        for (int kst = 0; kst < 2; kst++) {
            const int ko = kw + kst * 8;
            uint32_t afr[2][4];
#pragma unroll
            for (int mt = 0; mt < 2; mt++)
                ldmx4(afr[mt], qbase + q_lane_off + (uint32_t)((mt * 16 * 132 + ko) * 4));
#pragma unroll
            for (int nt = 0; nt < 3; nt++) {
                uint32_t bfr[2];
                ldmx2(bfr, kbase + k_lane_off + (uint32_t)((nt * 8 * 132 + ko) * 4));
#pragma unroll
                for (int mt = 0; mt < 2; mt++)
                    mma_16x8x16(acc[mt][nt], afr[mt], bfr);
            }
        }
    }
    __syncthreads();

    const int lr = lane >> 2;
    const int lc = lane & 3;
    float* rw = red + wid * 576;
#pragma unroll
    for (int mt = 0; mt < 2; mt++) {
        int r0 = mt * 16 + lr;
#pragma unroll
        for (int nt = 0; nt < 3; nt++) {
            int cc = nt * 8 + lc * 2;
            rw[r0 * 24 + cc]     = acc[mt][nt][0];
            rw[r0 * 24 + cc + 1] = acc[mt][nt][1];
            if (mt == 0) {
                rw[(r0 + 8) * 24 + cc]     = acc[mt][nt][2];
                rw[(r0 + 8) * 24 + cc + 1] = acc[mt][nt][3];
            }
        }
    }
    __syncthreads();

    float* Sp = &g_S[t][b][h][0];
    for (int i = tid; i < 576; i += 256) {
        float s = 0.f;
#pragma unroll
        for (int w = 0; w < 8; w++) s += red[w * 576 + i];
        atomicAdd(&Sp[i], s);
    }
}

// ---------------- K4: scale + softmax + M = wproj @ blockdiag(attn), fp16 out ----------------
__global__ void k4_softmax_M(const float* __restrict__ wproj,
                             const float* __restrict__ temp)
{
    int t = blockIdx.x >> 3, b = blockIdx.x & 7;
    int qs = (t == 0) ? 1 : 0;
    int kstream = 1 - qs;
    __shared__ float attn[C_IN][HD + 1];
    __shared__ float invq[C_IN], invk[C_IN];

    int tid = threadIdx.x;                 // 192 ; tid = h*HD + c
    {
        invq[tid] = 1.f / fmaxf(sqrtf(g_css[qs * 8 + b][tid]), 1e-12f);
        invk[tid] = 1.f / fmaxf(sqrtf(g_css[kstream * 8 + b][C_IN + tid]), 1e-12f);
    }
    __syncthreads();
    {
        int h = tid / HD, c = tid % HD;
        float tp = temp[h];
        float iq = invq[tid];
        float row[HD];
        float mx = -1e30f;
#pragma unroll
        for (int d = 0; d < HD; d++) {
            float v = g_S[t][b][h][c * HD + d] * iq * invk[h * HD + d] * tp;
            row[d] = v;
            mx = fmaxf(mx, v);
        }
        float sum = 0.f;
#pragma unroll
        for (int d = 0; d < HD; d++) { row[d] = expf(row[d] - mx); sum += row[d]; }
        float inv = 1.f / sum;
#pragma unroll
        for (int d = 0; d < HD; d++) attn[tid][d] = row[d] * inv;
    }
    __syncthreads();

    int o = tid;
    const float* wp = wproj + (size_t)o * C_IN;
    __half* Mrow = &g_M[t][b][(size_t)o * C_IN];
    for (int h = 0; h < HEADS; h++) {
        float wreg[HD];
#pragma unroll
        for (int i = 0; i < HD; i++) wreg[i] = wp[h * HD + i];
#pragma unroll
        for (int j = 0; j < HD; j++) {
            float s = 0.f;
#pragma unroll
            for (int i = 0; i < HD; i++) s += wreg[i] * attn[h * HD + i][j];
            Mrow[h * HD + j] = __float2half(s);
        }
    }
}

// ---------------- launch ----------------
extern "C" void kernel_launch(void* const* d_in, const int* in_sizes, int n_in,
                              void* d_out, int out_size)
{
    const float* rgb   = (const float*)d_in[0];
    const float* ir    = (const float*)d_in[1];
    const float* wqkv  = (const float*)d_in[2];
    const float* wdw   = (const float*)d_in[3];
    const float* wproj = (const float*)d_in[4];
    const float* temp  = (const float*)d_in[5];
    float* out = (float*)d_out;

    k0_zero<<<432, 256>>>(wqkv);
    k_nop1<<<1, 32>>>();     // keep ncu's profiled slot on k1_qkv
    k_nop2<<<1, 32>>>();

    dim3 g1(HW / 64, 3, 16);      // n0: 64-wide tiles; m0: 0,192,384
    k1_qkv<<<g1, 256>>>(rgb, ir);

    dim3 g2(2, C3, 16);           // 64 rows x 128 cols per block
    k2_dw<<<g2, 256>>>(wdw);

    dim3 g3(8, NB * HEADS, 2);    // K-slices of 2048
    k3_gram<<<g3, 256>>>();

    k4_softmax_M<<<16, 192>>>(wproj, temp);

    dim3 g5(HW / 64, 1, 16);      // single m pass (192 rows)
    k5_out<<<g5, 256>>>(out);
}

// round 16
// speedup vs baseline: 1.5208x; 1.0579x over previous
#include <cuda_runtime.h>
#include <cuda_fp16.h>
#include <cstdint>
#include <math.h>

// ---------------- problem constants ----------------
#define HW     16384      // 128*128
#define WIMG   128
#define C_IN   192
#define C3     576        // 3*C_IN
#define NB     8
#define HEADS  8
#define HD     24

// ---------------- scratch ----------------
__device__ __align__(16) __half g_y  [16][C3 * HW];
__device__ __align__(16) __half g_qkv[16][C3 * HW];
__device__ __align__(16) __half g_wh [C3 * C_IN];          // wqkv fp16
__device__ float  g_S  [2][NB][HEADS][HD * HD];
__device__ float  g_css[16][C3];
__device__ __align__(16) __half g_M  [2][NB][C_IN * C_IN]; // fused proj, fp16

// ---------------- K0: zero accumulators + convert weights ----------------
__global__ void k0_zero(const float* __restrict__ wqkv) {
    int idx = blockIdx.x * 256 + threadIdx.x;
    const int nS = 2 * NB * HEADS * HD * HD;
    const int nC = 16 * C3;
    if (idx < nS) (&g_S[0][0][0][0])[idx] = 0.f;
    if (idx < nC) (&g_css[0][0])[idx] = 0.f;
    if (idx < C3 * C_IN) g_wh[idx] = __float2half(wqkv[idx]);
}

// no-op shims so ncu's fixed skip-count lands on k1_qkv
__global__ void k_nop1() {}
__global__ void k_nop2() {}

// ---------------- fp16 / mma / async helpers ----------------
__device__ __forceinline__ uint32_t pack2(float a, float b) {
    __half2 h = __floats2half2_rn(a, b);
    return *(uint32_t*)&h;
}
__device__ __forceinline__ void mma_16x8x16(float* c, const uint32_t* a, const uint32_t* b) {
    asm volatile(
        "mma.sync.aligned.m16n8k16.row.col.f32.f16.f16.f32 "
        "{%0,%1,%2,%3}, {%4,%5,%6,%7}, {%8,%9}, {%0,%1,%2,%3};"
        : "+f"(c[0]), "+f"(c[1]), "+f"(c[2]), "+f"(c[3])
        : "r"(a[0]), "r"(a[1]), "r"(a[2]), "r"(a[3]), "r"(b[0]), "r"(b[1]));
}
__device__ __forceinline__ void ldmx4(uint32_t* r, uint32_t addr) {
    asm volatile("ldmatrix.sync.aligned.m8n8.x4.shared.b16 {%0,%1,%2,%3}, [%4];"
        : "=r"(r[0]), "=r"(r[1]), "=r"(r[2]), "=r"(r[3]) : "r"(addr));
}
__device__ __forceinline__ void ldmx4t(uint32_t* r, uint32_t addr) {
    asm volatile("ldmatrix.sync.aligned.m8n8.x4.trans.shared.b16 {%0,%1,%2,%3}, [%4];"
        : "=r"(r[0]), "=r"(r[1]), "=r"(r[2]), "=r"(r[3]) : "r"(addr));
}
__device__ __forceinline__ void ldmx2(uint32_t* r, uint32_t addr) {
    asm volatile("ldmatrix.sync.aligned.m8n8.x2.shared.b16 {%0,%1}, [%2];"
        : "=r"(r[0]), "=r"(r[1]) : "r"(addr));
}
__device__ __forceinline__ uint32_t sh_addr(const void* p) {
    return (uint32_t)__cvta_generic_to_shared(p);
}
__device__ __forceinline__ void cp_async16(uint32_t dst, const void* src) {
    asm volatile("cp.async.cg.shared.global [%0], [%1], 16;" :: "r"(dst), "l"(src));
}
#define CP_COMMIT() asm volatile("cp.async.commit_group;" ::: "memory")
#define CP_WAIT1()  asm volatile("cp.async.wait_group 1;"  ::: "memory")

// ---------------- fp16 mma GEMM, 3-stage pipeline ----------------
// C[m0:m0+192, n0:n0+64] = A(.,192)@B(192,HW). 256 threads, 8 warps (4Mx2N),
// warp tile 48x32, BK=32, 6 chunks, 3 smem slots, wait_group 1.
#define AS_SLOT 15360          // 192*20*4 bytes per slot
#define BS_SLOT 4608           // 32*36*4 bytes per slot
#define GEMM_SMEM (3 * AS_SLOT + 3 * BS_SLOT)   // 59904 B

template<bool B_HALF, bool C_HALF>
__device__ __forceinline__ void gemm_mma_192x64(
    const __half* __restrict__ A, const void* __restrict__ Bv, void* __restrict__ Cv,
    int m0, int n0)
{
    extern __shared__ __align__(16) char dsm[];
    const uint32_t As_base = sh_addr(dsm);
    const uint32_t Bs_base = As_base + 3 * AS_SLOT;

    const int tid  = threadIdx.x;
    const int wid  = tid >> 5;
    const int lane = tid & 31;
    const int warp_m = wid & 3;           // 0..3 -> 48 rows
    const int warp_n = wid >> 2;          // 0..1 -> 32 cols
    const int lr = lane >> 2;
    const int lc = lane & 3;

    const int ar16 = tid >> 2;            // A stage: row (+64it)
    const int aq16 = tid & 3;
    const int bhr = tid >> 3;             // B fp16 stage
    const int bhq = tid & 7;
    const int bk = tid >> 4;              // B fp32 stage
    const int bn4 = (tid & 15) * 4;

    const __half* Ap = A + (size_t)(m0 + ar16) * 192 + aq16 * 8;
    const float*  Bpf = B_HALF ? nullptr : ((const float*)Bv + (size_t)bk * HW + n0 + bn4);
    const __half* Bph = B_HALF ? ((const __half*)Bv + (size_t)bhr * HW + n0 + bhq * 8) : nullptr;

    const int lg = lane >> 3;
    const int lrow = lane & 7;
    const uint32_t a_lane_off = (uint32_t)((((lg & 1) << 3) + lrow) * 20 + ((lg >> 1) << 2)) * 4;
    const int bj = lane >> 3;
    const uint32_t b_lane_off =
        (uint32_t)((((bj & 1) << 3) + lrow) * 36 + ((bj >> 1) << 2) + warp_n * 16) * 4;

    const uint32_t as_st = As_base + (uint32_t)((ar16 * 20 + aq16 * 4) * 4);
    const uint32_t bs_st = Bs_base + (uint32_t)((bhr * 36 + bhq * 4) * 4);
    uint32_t* BsW = (uint32_t*)(dsm + 3 * AS_SLOT);   // word view for fp32-path STS

    uint2 bu[2];   // fp32-B register staging

    auto stageA = [&](int slot, int ch) {
        const __half* src = Ap + ch * 32;
        uint32_t dst = as_st + (uint32_t)slot * AS_SLOT;
#pragma unroll
        for (int it = 0; it < 3; it++)
            cp_async16(dst + (uint32_t)(it * 64 * 20 * 4), src + (size_t)it * 64 * 192);
    };
    auto stageB_async = [&](int slot, int ch) {
        cp_async16(bs_st + (uint32_t)slot * BS_SLOT, Bph + (size_t)(ch * 32) * HW);
    };
    auto loadB = [&](int ch) {
#pragma unroll
        for (int p = 0; p < 2; p++) {
            float4 v = *(const float4*)(Bpf + (size_t)(ch * 32 + p * 16) * HW);
            bu[p].x = pack2(v.x, v.y);
            bu[p].y = pack2(v.z, v.w);
        }
    };
    auto stsB = [&](int slot) {
        uint32_t* p = BsW + slot * (BS_SLOT / 4);
#pragma unroll
        for (int q = 0; q < 2; q++)
            *(uint2*)&p[(bk + q * 16) * 36 + (bn4 >> 1)] = bu[q];
    };

    // prologue: chunks 0,1 into slots 0,1
    stageA(0, 0);
    if (B_HALF) stageB_async(0, 0);
    CP_COMMIT();
    stageA(1, 1);
    if (B_HALF) stageB_async(1, 1);
    CP_COMMIT();
    if (!B_HALF) { loadB(0); stsB(0); loadB(1); stsB(1); }

    float acc[3][4][4];
#pragma unroll
    for (int i = 0; i < 3; i++)
#pragma unroll
        for (int j = 0; j < 4; j++)
#pragma unroll
            for (int q = 0; q < 4; q++) acc[i][j][q] = 0.f;

    int cslot = 0, sslot = 2;
    for (int ch = 0; ch < 6; ch++) {
        CP_WAIT1();             // chunk ch's group retired (per-thread)
        __syncthreads();        // all threads' slot writes visible; prior readers done
        if (ch < 4) {
            if (!B_HALF) loadB(ch + 2);      // LDG early: latency hidden by compute
            stageA(sslot, ch + 2);
            if (B_HALF) stageB_async(sslot, ch + 2);
        }
        CP_COMMIT();            // uniform: empty group when ch>=4 keeps FIFO math
        const uint32_t Asb = As_base + (uint32_t)cslot * AS_SLOT + a_lane_off;
        const uint32_t Bsb = Bs_base + (uint32_t)cslot * BS_SLOT + b_lane_off;
#pragma unroll
        for (int kst = 0; kst < 2; kst++) {
            uint32_t afr[3][4];
#pragma unroll
            for (int mt = 0; mt < 3; mt++)
                ldmx4(afr[mt], Asb + (uint32_t)(((warp_m * 48 + mt * 16) * 20 + kst * 8) * 4));
#pragma unroll
            for (int ntp = 0; ntp < 2; ntp++) {
                uint32_t bfr4[4];
                ldmx4t(bfr4, Bsb + (uint32_t)((kst * 16 * 36 + ntp * 8) * 4));
#pragma unroll
                for (int mt = 0; mt < 3; mt++) {
                    mma_16x8x16(acc[mt][ntp * 2],     afr[mt], &bfr4[0]);
                    mma_16x8x16(acc[mt][ntp * 2 + 1], afr[mt], &bfr4[2]);
                }
            }
        }
        if (ch < 4 && !B_HALF) stsB(sslot);  // read 2 iters later, 2 barriers between
        cslot = (cslot == 2) ? 0 : cslot + 1;
        sslot = (sslot == 2) ? 0 : sslot + 1;
    }

#pragma unroll
    for (int mt = 0; mt < 3; mt++) {
        int row = m0 + warp_m * 48 + mt * 16 + lr;
#pragma unroll
        for (int nt = 0; nt < 4; nt++) {
            int col = n0 + warp_n * 32 + nt * 8 + lc * 2;
            if (C_HALF) {
                __half* Ch = (__half*)Cv;
                *(uint32_t*)(Ch + (size_t)row * HW + col)       = pack2(acc[mt][nt][0], acc[mt][nt][1]);
                *(uint32_t*)(Ch + (size_t)(row + 8) * HW + col) = pack2(acc[mt][nt][2], acc[mt][nt][3]);
            } else {
                float* Cf = (float*)Cv;
                *(float2*)(Cf + (size_t)row * HW + col)       = make_float2(acc[mt][nt][0], acc[mt][nt][1]);
                *(float2*)(Cf + (size_t)(row + 8) * HW + col) = make_float2(acc[mt][nt][2], acc[mt][nt][3]);
            }
        }
    }
}

// ---------------- K1: 1x1 qkv conv ----------------
__global__ void __launch_bounds__(256, 2)
k1_qkv(const float* __restrict__ rgb, const float* __restrict__ ir)
{
    int z = blockIdx.z, s = z >> 3, b = z & 7;
    const float* x = (s ? ir : rgb) + (size_t)b * C_IN * HW;
    gemm_mma_192x64<false, true>(g_wh, x, g_y[z], blockIdx.y * 192, blockIdx.x * 64);
}

// ---------------- K5: out = M @ V ----------------
__global__ void __launch_bounds__(256, 2)
k5_out(float* __restrict__ out)
{
    int z = blockIdx.z;
    const __half* A = g_M[z >> 3][z & 7];
    const __half* V = g_qkv[z] + (size_t)(2 * C_IN) * HW;
    float* C = out + (size_t)z * C_IN * HW;
    gemm_mma_192x64<true, false>(A, V, C, 0, blockIdx.x * 64);
}

// ---------------- K2: depthwise 3x3 SAME via smem tile ----------------
#define K2_STRIDE 136
__global__ void k2_dw(const float* __restrict__ wdw)
{
    __shared__ __align__(16) __half sm[66 * K2_STRIDE];

    int z  = blockIdx.z;
    int ch = blockIdx.y;
    const __half* yin = g_y[z]  + (size_t)ch * HW;
    __half*       out = g_qkv[z] + (size_t)ch * HW;
    int row0 = blockIdx.x * 64;

    for (int idx = threadIdx.x; idx < 66 * 16; idx += 256) {
        int r  = idx >> 4;
        int c8 = (idx & 15) * 8;
        int ry = row0 - 1 + r;
        uint4 v = make_uint4(0u, 0u, 0u, 0u);
        if (ry >= 0 && ry < WIMG) v = *(const uint4*)&yin[(size_t)ry * WIMG + c8];
        *(uint4*)&sm[r * K2_STRIDE + c8] = v;
    }

    const float* w = wdw + ch * 9;
    float wr[3][3];
#pragma unroll
    for (int i = 0; i < 9; i++) wr[i / 3][i % 3] = w[i];
    __syncthreads();

    int t = threadIdx.x;
    int xx = (t & 15) * 8;
    int rl = (t >> 4) * 4;
    bool xm = (xx > 0), xp = (xx < 120);

    float f[6][10];
#pragma unroll
    for (int r = 0; r < 6; r++) {
        const __half* rp = &sm[(rl + r) * K2_STRIDE];
#pragma unroll
        for (int i = 0; i < 8; i++) f[r][i + 1] = __half2float(rp[xx + i]);
        f[r][0] = xm ? __half2float(rp[xx - 1]) : 0.f;
        f[r][9] = xp ? __half2float(rp[xx + 8]) : 0.f;
    }

    float ss = 0.f;
#pragma unroll
    for (int r = 0; r < 4; r++) {
        float o[8];
#pragma unroll
        for (int i = 0; i < 8; i++) {
            float acc = 0.f;
#pragma unroll
            for (int dr = 0; dr < 3; dr++)
                acc += wr[dr][0] * f[r + dr][i] + wr[dr][1] * f[r + dr][i + 1]
                     + wr[dr][2] * f[r + dr][i + 2];
            o[i] = acc;
            ss += acc * acc;
        }
        uint4 ov;
        ov.x = pack2(o[0], o[1]);
        ov.y = pack2(o[2], o[3]);
        ov.z = pack2(o[4], o[5]);
        ov.w = pack2(o[6], o[7]);
        *(uint4*)&out[(size_t)(row0 + rl + r) * WIMG + xx] = ov;
    }

#pragma unroll
    for (int off = 16; off; off >>= 1) ss += __shfl_xor_sync(0xFFFFFFFFu, ss, off);
    if ((threadIdx.x & 31) == 0) atomicAdd(&g_css[z][ch], ss);
}

// ---------------- K3: channel Gram via tensor cores + ldmatrix ----------------
__global__ void __launch_bounds__(256)
k3_gram()
{
    __shared__ __align__(16) char smraw[16896 + 12672];
    __half2 (*qsm)[132] = reinterpret_cast<__half2(*)[132]>(smraw);
    __half2 (*ksm)[132] = reinterpret_cast<__half2(*)[132]>(smraw + 16896);
    float* red = reinterpret_cast<float*>(smraw);

    int t  = blockIdx.z;
    int bh = blockIdx.y;
    int b = bh >> 3, h = bh & 7;
    int n0 = blockIdx.x * 2048;

    int qs = (t == 0) ? 1 : 0;
    int kstream = 1 - qs;
    const __half* qb = g_qkv[qs * 8 + b]      + (size_t)(h * HD) * HW + n0;
    const __half* kb = g_qkv[kstream * 8 + b] + (size_t)(C_IN + h * HD) * HW + n0;

    const int tid  = threadIdx.x;
    const int wid  = tid >> 5;
    const int lane = tid & 31;
    const int kw = wid * 16;

    const int lg = lane >> 3;
    const int lrow = lane & 7;
    const uint32_t q_lane_off = (uint32_t)((((lg & 1) << 3) + lrow) * 132 + ((lg >> 1) << 2)) * 4;
    const uint32_t k_lane_off = (uint32_t)(((lane & 15) & 7) * 132 + (((lane & 15) >> 3) << 2)) * 4;
    const uint32_t qbase = sh_addr(&qsm[0][0]);
    const uint32_t kbase = sh_addr(&ksm[0][0]);

    float acc[2][3][4];
#pragma unroll
    for (int i = 0; i < 2; i++)
#pragma unroll
        for (int j = 0; j < 3; j++)
#pragma unroll
            for (int q = 0; q < 4; q++) acc[i][j][q] = 0.f;

    for (int c0 = 0; c0 < 2048; c0 += 256) {
        __syncthreads();
        for (int i = tid; i < 1536; i += 256) {
            int arr = (i >= 768);
            int li  = arr ? (i - 768) : i;
            int row = li >> 5;
            int v8  = (li & 31) * 8;
            const __half* src = arr ? kb : qb;
            uint4 v = *(const uint4*)&src[(size_t)row * HW + c0 + v8];
            if (arr) *(uint4*)&ksm[row][v8 >> 1] = v;
            else     *(uint4*)&qsm[row][v8 >> 1] = v;
        }
        __syncthreads();
#pragma unroll
        for (int kst = 0; kst < 2; kst++) {
            const int ko = kw + kst * 8;
            uint32_t afr[2][4];
#pragma unroll
            for (int mt = 0; mt < 2; mt++)
                ldmx4(afr[mt], qbase + q_lane_off + (uint32_t)((mt * 16 * 132 + ko) * 4));
#pragma unroll
            for (int nt = 0; nt < 3; nt++) {
                uint32_t bfr[2];
                ldmx2(bfr, kbase + k_lane_off + (uint32_t)((nt * 8 * 132 + ko) * 4));
#pragma unroll
                for (int mt = 0; mt < 2; mt++)
                    mma_16x8x16(acc[mt][nt], afr[mt], bfr);
            }
        }
    }
    __syncthreads();

    const int lr = lane >> 2;
    const int lc = lane & 3;
    float* rw = red + wid * 576;
#pragma unroll
    for (int mt = 0; mt < 2; mt++) {
        int r0 = mt * 16 + lr;
#pragma unroll
        for (int nt = 0; nt < 3; nt++) {
            int cc = nt * 8 + lc * 2;
            rw[r0 * 24 + cc]     = acc[mt][nt][0];
            rw[r0 * 24 + cc + 1] = acc[mt][nt][1];
            if (mt == 0) {
                rw[(r0 + 8) * 24 + cc]     = acc[mt][nt][2];
                rw[(r0 + 8) * 24 + cc + 1] = acc[mt][nt][3];
            }
        }
    }
    __syncthreads();

    float* Sp = &g_S[t][b][h][0];
    for (int i = tid; i < 576; i += 256) {
        float s = 0.f;
#pragma unroll
        for (int w = 0; w < 8; w++) s += red[w * 576 + i];
        atomicAdd(&Sp[i], s);
    }
}

// ---------------- K4: scale + softmax + M = wproj @ blockdiag(attn), fp16 out ----------------
__global__ void k4_softmax_M(const float* __restrict__ wproj,
                             const float* __restrict__ temp)
{
    int t = blockIdx.x >> 3, b = blockIdx.x & 7;
    int qs = (t == 0) ? 1 : 0;
    int kstream = 1 - qs;
    __shared__ float attn[C_IN][HD + 1];
    __shared__ float invq[C_IN], invk[C_IN];

    int tid = threadIdx.x;                 // 192 ; tid = h*HD + c
    {
        invq[tid] = 1.f / fmaxf(sqrtf(g_css[qs * 8 + b][tid]), 1e-12f);
        invk[tid] = 1.f / fmaxf(sqrtf(g_css[kstream * 8 + b][C_IN + tid]), 1e-12f);
    }
    __syncthreads();
    {
        int h = tid / HD, c = tid % HD;
        float tp = temp[h];
        float iq = invq[tid];
        float row[HD];
        float mx = -1e30f;
#pragma unroll
        for (int d = 0; d < HD; d++) {
            float v = g_S[t][b][h][c * HD + d] * iq * invk[h * HD + d] * tp;
            row[d] = v;
            mx = fmaxf(mx, v);
        }
        float sum = 0.f;
#pragma unroll
        for (int d = 0; d < HD; d++) { row[d] = expf(row[d] - mx); sum += row[d]; }
        float inv = 1.f / sum;
#pragma unroll
        for (int d = 0; d < HD; d++) attn[tid][d] = row[d] * inv;
    }
    __syncthreads();

    int o = tid;
    const float* wp = wproj + (size_t)o * C_IN;
    __half* Mrow = &g_M[t][b][(size_t)o * C_IN];
    for (int h = 0; h < HEADS; h++) {
        float wreg[HD];
#pragma unroll
        for (int i = 0; i < HD; i++) wreg[i] = wp[h * HD + i];
#pragma unroll
        for (int j = 0; j < HD; j++) {
            float s = 0.f;
#pragma unroll
            for (int i = 0; i < HD; i++) s += wreg[i] * attn[h * HD + i][j];
            Mrow[h * HD + j] = __float2half(s);
        }
    }
}

// ---------------- launch ----------------
extern "C" void kernel_launch(void* const* d_in, const int* in_sizes, int n_in,
                              void* d_out, int out_size)
{
    const float* rgb   = (const float*)d_in[0];
    const float* ir    = (const float*)d_in[1];
    const float* wqkv  = (const float*)d_in[2];
    const float* wdw   = (const float*)d_in[3];
    const float* wproj = (const float*)d_in[4];
    const float* temp  = (const float*)d_in[5];
    float* out = (float*)d_out;

    // opt-in >48KB dynamic smem (host attribute set; not a captured op)
    cudaFuncSetAttribute(k1_qkv, cudaFuncAttributeMaxDynamicSharedMemorySize, GEMM_SMEM);
    cudaFuncSetAttribute(k5_out, cudaFuncAttributeMaxDynamicSharedMemorySize, GEMM_SMEM);

    k0_zero<<<432, 256>>>(wqkv);
    k_nop1<<<1, 32>>>();     // keep ncu's profiled slot on k1_qkv
    k_nop2<<<1, 32>>>();

    dim3 g1(HW / 64, 3, 16);      // n0: 64-wide tiles; m0: 0,192,384
    k1_qkv<<<g1, 256, GEMM_SMEM>>>(rgb, ir);

    dim3 g2(2, C3, 16);           // 64 rows x 128 cols per block
    k2_dw<<<g2, 256>>>(wdw);

    dim3 g3(8, NB * HEADS, 2);    // K-slices of 2048
    k3_gram<<<g3, 256>>>();

    k4_softmax_M<<<16, 192>>>(wproj, temp);

    dim3 g5(HW / 64, 1, 16);      // single m pass (192 rows)
    k5_out<<<g5, 256, GEMM_SMEM>>>(out);
}

// round 17
// speedup vs baseline: 1.6010x; 1.0528x over previous
#include <cuda_runtime.h>
#include <cuda_fp16.h>
#include <cstdint>
#include <math.h>

// ---------------- problem constants ----------------
#define HW     16384      // 128*128
#define WIMG   128
#define C_IN   192
#define C3     576        // 3*C_IN
#define NB     8
#define HEADS  8
#define HD     24

// ---------------- scratch ----------------
__device__ __align__(16) __half g_y  [16][C3 * HW];
__device__ __align__(16) __half g_qkv[16][C3 * HW];
__device__ __align__(16) __half g_wh [C3 * C_IN];          // wqkv fp16
__device__ float  g_S  [2][NB][HEADS][HD * HD];
__device__ float  g_css[16][C3];
__device__ __align__(16) __half g_M  [2][NB][C_IN * C_IN]; // fused proj, fp16

// ---------------- K0: zero accumulators + convert weights ----------------
__global__ void k0_zero(const float* __restrict__ wqkv) {
    int idx = blockIdx.x * 256 + threadIdx.x;
    const int nS = 2 * NB * HEADS * HD * HD;
    const int nC = 16 * C3;
    if (idx < nS) (&g_S[0][0][0][0])[idx] = 0.f;
    if (idx < nC) (&g_css[0][0])[idx] = 0.f;
    if (idx < C3 * C_IN) g_wh[idx] = __float2half(wqkv[idx]);
}

// no-op shims so ncu's fixed skip-count lands on k1_qkv
__global__ void k_nop1() {}
__global__ void k_nop2() {}

// ---------------- fp16 / mma / async helpers ----------------
__device__ __forceinline__ uint32_t pack2(float a, float b) {
    __half2 h = __floats2half2_rn(a, b);
    return *(uint32_t*)&h;
}
__device__ __forceinline__ void mma_16x8x16(float* c, const uint32_t* a, const uint32_t* b) {
    asm volatile(
        "mma.sync.aligned.m16n8k16.row.col.f32.f16.f16.f32 "
        "{%0,%1,%2,%3}, {%4,%5,%6,%7}, {%8,%9}, {%0,%1,%2,%3};"
        : "+f"(c[0]), "+f"(c[1]), "+f"(c[2]), "+f"(c[3])
        : "r"(a[0]), "r"(a[1]), "r"(a[2]), "r"(a[3]), "r"(b[0]), "r"(b[1]));
}
__device__ __forceinline__ void ldmx4(uint32_t* r, uint32_t addr) {
    asm volatile("ldmatrix.sync.aligned.m8n8.x4.shared.b16 {%0,%1,%2,%3}, [%4];"
        : "=r"(r[0]), "=r"(r[1]), "=r"(r[2]), "=r"(r[3]) : "r"(addr));
}
__device__ __forceinline__ void ldmx4t(uint32_t* r, uint32_t addr) {
    asm volatile("ldmatrix.sync.aligned.m8n8.x4.trans.shared.b16 {%0,%1,%2,%3}, [%4];"
        : "=r"(r[0]), "=r"(r[1]), "=r"(r[2]), "=r"(r[3]) : "r"(addr));
}
__device__ __forceinline__ void ldmx2(uint32_t* r, uint32_t addr) {
    asm volatile("ldmatrix.sync.aligned.m8n8.x2.shared.b16 {%0,%1}, [%2];"
        : "=r"(r[0]), "=r"(r[1]) : "r"(addr));
}
__device__ __forceinline__ uint32_t sh_addr(const void* p) {
    return (uint32_t)__cvta_generic_to_shared(p);
}
__device__ __forceinline__ void cp_async16(uint32_t dst, const void* src) {
    asm volatile("cp.async.cg.shared.global [%0], [%1], 16;" :: "r"(dst), "l"(src));
}
#define CP_COMMIT() asm volatile("cp.async.commit_group;" ::: "memory")
#define CP_WAIT1()  asm volatile("cp.async.wait_group 1;"  ::: "memory")

#define AS_SLOT 15360          // 192*20*4 bytes per A slot
#define BS_SLOT 4608           // 32*36*4 bytes per B chunk
// k1: B resident for all K (6 chunks) + 3 A slots
#define K1_SMEM (6 * BS_SLOT + 3 * AS_SLOT)     // 27648 + 46080 = 73728
// k5: 3 slots each (as round 16)
#define K5_SMEM (3 * AS_SLOT + 3 * BS_SLOT)     // 59904

// ---------------- K1: B-resident GEMM. C[0:576, n0:n0+64] = W(576x192) @ x(192,HW) ----------
// 256 threads, 8 warps (4Mx2N), warp tile 48x32. B (x, fp32->fp16) staged ONCE for all K;
// A (weights, fp16) flows through a 3-slot cp.async pipeline across 3 m-passes x 6 chunks.
__global__ void __launch_bounds__(256, 2)
k1_qkv(const float* __restrict__ rgb, const float* __restrict__ ir)
{
    extern __shared__ __align__(16) char dsm[];
    const uint32_t Bs_base = sh_addr(dsm);
    const uint32_t As_base = Bs_base + 6 * BS_SLOT;
    uint32_t* BsW = (uint32_t*)dsm;

    int z = blockIdx.z, s = z >> 3, b = z & 7;
    const float* x = (s ? ir : rgb) + (size_t)b * C_IN * HW;
    __half* C = g_y[z];
    const int n0 = blockIdx.x * 64;

    const int tid  = threadIdx.x;
    const int wid  = tid >> 5;
    const int lane = tid & 31;
    const int warp_m = wid & 3;
    const int warp_n = wid >> 2;
    const int lr = lane >> 2;
    const int lc = lane & 3;

    // A staging (cp.async 16B): row = (tid>>2) + 64*it within the m-pass
    const int ar16 = tid >> 2;
    const int aq16 = tid & 3;
    // B staging (fp32 -> fp16 regs -> STS): rows bk, bk+16 of each 32-k chunk
    const int bk = tid >> 4;
    const int bn4 = (tid & 15) * 4;
    const float* Bpf = x + (size_t)bk * HW + n0 + bn4;

    const int lg = lane >> 3;
    const int lrow = lane & 7;
    const uint32_t a_lane_off = (uint32_t)((((lg & 1) << 3) + lrow) * 20 + ((lg >> 1) << 2)) * 4;
    const int bj = lane >> 3;
    const uint32_t b_lane_off =
        (uint32_t)((((bj & 1) << 3) + lrow) * 36 + ((bj >> 1) << 2) + warp_n * 16) * 4;

    const uint32_t as_st = As_base + (uint32_t)((ar16 * 20 + aq16 * 4) * 4);

    auto stageA = [&](int slot, int gchunk) {   // gchunk = mp*6 + ch
        int mp = gchunk / 6, ch = gchunk - mp * 6;
        const __half* src = g_wh + (size_t)(mp * 192 + ar16) * 192 + ch * 32 + aq16 * 8;
        uint32_t dst = as_st + (uint32_t)slot * AS_SLOT;
#pragma unroll
        for (int it = 0; it < 3; it++)
            cp_async16(dst + (uint32_t)(it * 64 * 20 * 4), src + (size_t)it * 64 * 192);
    };

    // prologue: A chunks 0,1 async; B full (6 chunks) via registers
    stageA(0, 0);
    CP_COMMIT();
    stageA(1, 1);
    CP_COMMIT();
#pragma unroll
    for (int ch = 0; ch < 6; ch++) {
        uint2 bu[2];
#pragma unroll
        for (int p = 0; p < 2; p++) {
            float4 v = *(const float4*)(Bpf + (size_t)(ch * 32 + p * 16) * HW);
            bu[p].x = pack2(v.x, v.y);
            bu[p].y = pack2(v.z, v.w);
        }
        uint32_t* pb = BsW + ch * (BS_SLOT / 4);
#pragma unroll
        for (int p = 0; p < 2; p++)
            *(uint2*)&pb[(bk + p * 16) * 36 + (bn4 >> 1)] = bu[p];
    }

    float acc[3][4][4];
#pragma unroll
    for (int i = 0; i < 3; i++)
#pragma unroll
        for (int j = 0; j < 4; j++)
#pragma unroll
            for (int q = 0; q < 4; q++) acc[i][j][q] = 0.f;

    int cslot = 0, sslot = 2;
    for (int it = 0; it < 18; it++) {           // (mp, ch) = (it/6, it%6)
        CP_WAIT1();
        __syncthreads();
        if (it < 16) stageA(sslot, it + 2);
        CP_COMMIT();
        const int ch = it % 6;
        const uint32_t Asb = As_base + (uint32_t)cslot * AS_SLOT + a_lane_off;
        const uint32_t Bsb = Bs_base + (uint32_t)ch * BS_SLOT + b_lane_off;
#pragma unroll
        for (int kst = 0; kst < 2; kst++) {
            uint32_t afr[3][4];
#pragma unroll
            for (int mt = 0; mt < 3; mt++)
                ldmx4(afr[mt], Asb + (uint32_t)(((warp_m * 48 + mt * 16) * 20 + kst * 8) * 4));
#pragma unroll
            for (int ntp = 0; ntp < 2; ntp++) {
                uint32_t bfr4[4];
                ldmx4t(bfr4, Bsb + (uint32_t)((kst * 16 * 36 + ntp * 8) * 4));
#pragma unroll
                for (int mt = 0; mt < 3; mt++) {
                    mma_16x8x16(acc[mt][ntp * 2],     afr[mt], &bfr4[0]);
                    mma_16x8x16(acc[mt][ntp * 2 + 1], afr[mt], &bfr4[2]);
                }
            }
        }
        if (ch == 5) {                          // end of m-pass: write + reset acc
            int m0 = (it / 6) * 192;
#pragma unroll
            for (int mt = 0; mt < 3; mt++) {
                int row = m0 + warp_m * 48 + mt * 16 + lr;
#pragma unroll
                for (int nt = 0; nt < 4; nt++) {
                    int col = n0 + warp_n * 32 + nt * 8 + lc * 2;
                    *(uint32_t*)(C + (size_t)row * HW + col)       = pack2(acc[mt][nt][0], acc[mt][nt][1]);
                    *(uint32_t*)(C + (size_t)(row + 8) * HW + col) = pack2(acc[mt][nt][2], acc[mt][nt][3]);
#pragma unroll
                    for (int q = 0; q < 4; q++) acc[mt][nt][q] = 0.f;
                }
            }
        }
        cslot = (cslot == 2) ? 0 : cslot + 1;
        sslot = (sslot == 2) ? 0 : sslot + 1;
    }
}

// ---------------- K5 GEMM (3-stage, both operands fp16 async) ----------------
__global__ void __launch_bounds__(256, 2)
k5_out(float* __restrict__ out)
{
    extern __shared__ __align__(16) char dsm[];
    const uint32_t As_base = sh_addr(dsm);
    const uint32_t Bs_base = As_base + 3 * AS_SLOT;

    int z = blockIdx.z;
    const __half* A = g_M[z >> 3][z & 7];
    const __half* V = g_qkv[z] + (size_t)(2 * C_IN) * HW;
    float* C = out + (size_t)z * C_IN * HW;
    const int n0 = blockIdx.x * 64;

    const int tid  = threadIdx.x;
    const int wid  = tid >> 5;
    const int lane = tid & 31;
    const int warp_m = wid & 3;
    const int warp_n = wid >> 2;
    const int lr = lane >> 2;
    const int lc = lane & 3;

    const int ar16 = tid >> 2;
    const int aq16 = tid & 3;
    const int bhr = tid >> 3;
    const int bhq = tid & 7;

    const __half* Ap = A + (size_t)ar16 * 192 + aq16 * 8;
    const __half* Bph = V + (size_t)bhr * HW + n0 + bhq * 8;

    const int lg = lane >> 3;
    const int lrow = lane & 7;
    const uint32_t a_lane_off = (uint32_t)((((lg & 1) << 3) + lrow) * 20 + ((lg >> 1) << 2)) * 4;
    const int bj = lane >> 3;
    const uint32_t b_lane_off =
        (uint32_t)((((bj & 1) << 3) + lrow) * 36 + ((bj >> 1) << 2) + warp_n * 16) * 4;

    const uint32_t as_st = As_base + (uint32_t)((ar16 * 20 + aq16 * 4) * 4);
    const uint32_t bs_st = Bs_base + (uint32_t)((bhr * 36 + bhq * 4) * 4);

    auto stage = [&](int slot, int ch) {
        uint32_t dsta = as_st + (uint32_t)slot * AS_SLOT;
        const __half* srca = Ap + ch * 32;
#pragma unroll
        for (int it = 0; it < 3; it++)
            cp_async16(dsta + (uint32_t)(it * 64 * 20 * 4), srca + (size_t)it * 64 * 192);
        cp_async16(bs_st + (uint32_t)slot * BS_SLOT, Bph + (size_t)(ch * 32) * HW);
    };

    stage(0, 0); CP_COMMIT();
    stage(1, 1); CP_COMMIT();

    float acc[3][4][4];
#pragma unroll
    for (int i = 0; i < 3; i++)
#pragma unroll
        for (int j = 0; j < 4; j++)
#pragma unroll
            for (int q = 0; q < 4; q++) acc[i][j][q] = 0.f;

    int cslot = 0, sslot = 2;
    for (int ch = 0; ch < 6; ch++) {
        CP_WAIT1();
        __syncthreads();
        if (ch < 4) stage(sslot, ch + 2);
        CP_COMMIT();
        const uint32_t Asb = As_base + (uint32_t)cslot * AS_SLOT + a_lane_off;
        const uint32_t Bsb = Bs_base + (uint32_t)cslot * BS_SLOT + b_lane_off;
#pragma unroll
        for (int kst = 0; kst < 2; kst++) {
            uint32_t afr[3][4];
#pragma unroll
            for (int mt = 0; mt < 3; mt++)
                ldmx4(afr[mt], Asb + (uint32_t)(((warp_m * 48 + mt * 16) * 20 + kst * 8) * 4));
#pragma unroll
            for (int ntp = 0; ntp < 2; ntp++) {
                uint32_t bfr4[4];
                ldmx4t(bfr4, Bsb + (uint32_t)((kst * 16 * 36 + ntp * 8) * 4));
#pragma unroll
                for (int mt = 0; mt < 3; mt++) {
                    mma_16x8x16(acc[mt][ntp * 2],     afr[mt], &bfr4[0]);
                    mma_16x8x16(acc[mt][ntp * 2 + 1], afr[mt], &bfr4[2]);
                }
            }
        }
        cslot = (cslot == 2) ? 0 : cslot + 1;
        sslot = (sslot == 2) ? 0 : sslot + 1;
    }

#pragma unroll
    for (int mt = 0; mt < 3; mt++) {
        int row = warp_m * 48 + mt * 16 + lr;
#pragma unroll
        for (int nt = 0; nt < 4; nt++) {
            int col = n0 + warp_n * 32 + nt * 8 + lc * 2;
            *(float2*)(C + (size_t)row * HW + col)       = make_float2(acc[mt][nt][0], acc[mt][nt][1]);
            *(float2*)(C + (size_t)(row + 8) * HW + col) = make_float2(acc[mt][nt][2], acc[mt][nt][3]);
        }
    }
}

// ---------------- K2: depthwise 3x3 SAME via smem tile ----------------
#define K2_STRIDE 136
__global__ void k2_dw(const float* __restrict__ wdw)
{
    __shared__ __align__(16) __half sm[66 * K2_STRIDE];

    int z  = blockIdx.z;
    int ch = blockIdx.y;
    const __half* yin = g_y[z]  + (size_t)ch * HW;
    __half*       out = g_qkv[z] + (size_t)ch * HW;
    int row0 = blockIdx.x * 64;

    for (int idx = threadIdx.x; idx < 66 * 16; idx += 256) {
        int r  = idx >> 4;
        int c8 = (idx & 15) * 8;
        int ry = row0 - 1 + r;
        uint4 v = make_uint4(0u, 0u, 0u, 0u);
        if (ry >= 0 && ry < WIMG) v = *(const uint4*)&yin[(size_t)ry * WIMG + c8];
        *(uint4*)&sm[r * K2_STRIDE + c8] = v;
    }

    const float* w = wdw + ch * 9;
    float wr[3][3];
#pragma unroll
    for (int i = 0; i < 9; i++) wr[i / 3][i % 3] = w[i];
    __syncthreads();

    int t = threadIdx.x;
    int xx = (t & 15) * 8;
    int rl = (t >> 4) * 4;
    bool xm = (xx > 0), xp = (xx < 120);

    float f[6][10];
#pragma unroll
    for (int r = 0; r < 6; r++) {
        const __half* rp = &sm[(rl + r) * K2_STRIDE];
#pragma unroll
        for (int i = 0; i < 8; i++) f[r][i + 1] = __half2float(rp[xx + i]);
        f[r][0] = xm ? __half2float(rp[xx - 1]) : 0.f;
        f[r][9] = xp ? __half2float(rp[xx + 8]) : 0.f;
    }

    float ss = 0.f;
#pragma unroll
    for (int r = 0; r < 4; r++) {
        float o[8];
#pragma unroll
        for (int i = 0; i < 8; i++) {
            float acc = 0.f;
#pragma unroll
            for (int dr = 0; dr < 3; dr++)
                acc += wr[dr][0] * f[r + dr][i] + wr[dr][1] * f[r + dr][i + 1]
                     + wr[dr][2] * f[r + dr][i + 2];
            o[i] = acc;
            ss += acc * acc;
        }
        uint4 ov;
        ov.x = pack2(o[0], o[1]);
        ov.y = pack2(o[2], o[3]);
        ov.z = pack2(o[4], o[5]);
        ov.w = pack2(o[6], o[7]);
        *(uint4*)&out[(size_t)(row0 + rl + r) * WIMG + xx] = ov;
    }

#pragma unroll
    for (int off = 16; off; off >>= 1) ss += __shfl_xor_sync(0xFFFFFFFFu, ss, off);
    if ((threadIdx.x & 31) == 0) atomicAdd(&g_css[z][ch], ss);
}

// ---------------- K3: channel Gram via tensor cores + ldmatrix ----------------
__global__ void __launch_bounds__(256)
k3_gram()
{
    __shared__ __align__(16) char smraw[16896 + 12672];
    __half2 (*qsm)[132] = reinterpret_cast<__half2(*)[132]>(smraw);
    __half2 (*ksm)[132] = reinterpret_cast<__half2(*)[132]>(smraw + 16896);
    float* red = reinterpret_cast<float*>(smraw);

    int t  = blockIdx.z;
    int bh = blockIdx.y;
    int b = bh >> 3, h = bh & 7;
    int n0 = blockIdx.x * 2048;

    int qs = (t == 0) ? 1 : 0;
    int kstream = 1 - qs;
    const __half* qb = g_qkv[qs * 8 + b]      + (size_t)(h * HD) * HW + n0;
    const __half* kb = g_qkv[kstream * 8 + b] + (size_t)(C_IN + h * HD) * HW + n0;

    const int tid  = threadIdx.x;
    const int wid  = tid >> 5;
    const int lane = tid & 31;
    const int kw = wid * 16;

    const int lg = lane >> 3;
    const int lrow = lane & 7;
    const uint32_t q_lane_off = (uint32_t)((((lg & 1) << 3) + lrow) * 132 + ((lg >> 1) << 2)) * 4;
    const uint32_t k_lane_off = (uint32_t)(((lane & 15) & 7) * 132 + (((lane & 15) >> 3) << 2)) * 4;
    const uint32_t qbase = sh_addr(&qsm[0][0]);
    const uint32_t kbase = sh_addr(&ksm[0][0]);

    float acc[2][3][4];
#pragma unroll
    for (int i = 0; i < 2; i++)
#pragma unroll
        for (int j = 0; j < 3; j++)
#pragma unroll
            for (int q = 0; q < 4; q++) acc[i][j][q] = 0.f;

    for (int c0 = 0; c0 < 2048; c0 += 256) {
        __syncthreads();
        for (int i = tid; i < 1536; i += 256) {
            int arr = (i >= 768);
            int li  = arr ? (i - 768) : i;
            int row = li >> 5;
            int v8  = (li & 31) * 8;
            const __half* src = arr ? kb : qb;
            uint4 v = *(const uint4*)&src[(size_t)row * HW + c0 + v8];
            if (arr) *(uint4*)&ksm[row][v8 >> 1] = v;
            else     *(uint4*)&qsm[row][v8 >> 1] = v;
        }
        __syncthreads();
#pragma unroll
        for (int kst = 0; kst < 2; kst++) {
            const int ko = kw + kst * 8;
            uint32_t afr[2][4];
#pragma unroll
            for (int mt = 0; mt < 2; mt++)
                ldmx4(afr[mt], qbase + q_lane_off + (uint32_t)((mt * 16 * 132 + ko) * 4));
#pragma unroll
            for (int nt = 0; nt < 3; nt++) {
                uint32_t bfr[2];
                ldmx2(bfr, kbase + k_lane_off + (uint32_t)((nt * 8 * 132 + ko) * 4));
#pragma unroll
                for (int mt = 0; mt < 2; mt++)
                    mma_16x8x16(acc[mt][nt], afr[mt], bfr);
            }
        }
    }
    __syncthreads();

    const int lr = lane >> 2;
    const int lc = lane & 3;
    float* rw = red + wid * 576;
#pragma unroll
    for (int mt = 0; mt < 2; mt++) {
        int r0 = mt * 16 + lr;
#pragma unroll
        for (int nt = 0; nt < 3; nt++) {
            int cc = nt * 8 + lc * 2;
            rw[r0 * 24 + cc]     = acc[mt][nt][0];
            rw[r0 * 24 + cc + 1] = acc[mt][nt][1];
            if (mt == 0) {
                rw[(r0 + 8) * 24 + cc]     = acc[mt][nt][2];
                rw[(r0 + 8) * 24 + cc + 1] = acc[mt][nt][3];
            }
        }
    }
    __syncthreads();

    float* Sp = &g_S[t][b][h][0];
    for (int i = tid; i < 576; i += 256) {
        float s = 0.f;
#pragma unroll
        for (int w = 0; w < 8; w++) s += red[w * 576 + i];
        atomicAdd(&Sp[i], s);
    }
}

// ---------------- K4: scale + softmax + M = wproj @ blockdiag(attn), fp16 out ----------------
__global__ void k4_softmax_M(const float* __restrict__ wproj,
                             const float* __restrict__ temp)
{
    int t = blockIdx.x >> 3, b = blockIdx.x & 7;
    int qs = (t == 0) ? 1 : 0;
    int kstream = 1 - qs;
    __shared__ float attn[C_IN][HD + 1];
    __shared__ float invq[C_IN], invk[C_IN];

    int tid = threadIdx.x;                 // 192 ; tid = h*HD + c
    {
        invq[tid] = 1.f / fmaxf(sqrtf(g_css[qs * 8 + b][tid]), 1e-12f);
        invk[tid] = 1.f / fmaxf(sqrtf(g_css[kstream * 8 + b][C_IN + tid]), 1e-12f);
    }
    __syncthreads();
    {
        int h = tid / HD, c = tid % HD;
        float tp = temp[h];
        float iq = invq[tid];
        float row[HD];
        float mx = -1e30f;
#pragma unroll
        for (int d = 0; d < HD; d++) {
            float v = g_S[t][b][h][c * HD + d] * iq * invk[h * HD + d] * tp;
            row[d] = v;
            mx = fmaxf(mx, v);
        }
        float sum = 0.f;
#pragma unroll
        for (int d = 0; d < HD; d++) { row[d] = expf(row[d] - mx); sum += row[d]; }
        float inv = 1.f / sum;
#pragma unroll
        for (int d = 0; d < HD; d++) attn[tid][d] = row[d] * inv;
    }
    __syncthreads();

    int o = tid;
    const float* wp = wproj + (size_t)o * C_IN;
    __half* Mrow = &g_M[t][b][(size_t)o * C_IN];
    for (int h = 0; h < HEADS; h++) {
        float wreg[HD];
#pragma unroll
        for (int i = 0; i < HD; i++) wreg[i] = wp[h * HD + i];
#pragma unroll
        for (int j = 0; j < HD; j++) {
            float s = 0.f;
#pragma unroll
            for (int i = 0; i < HD; i++) s += wreg[i] * attn[h * HD + i][j];
            Mrow[h * HD + j] = __float2half(s);
        }
    }
}

// ---------------- launch ----------------
extern "C" void kernel_launch(void* const* d_in, const int* in_sizes, int n_in,
                              void* d_out, int out_size)
{
    const float* rgb   = (const float*)d_in[0];
    const float* ir    = (const float*)d_in[1];
    const float* wqkv  = (const float*)d_in[2];
    const float* wdw   = (const float*)d_in[3];
    const float* wproj = (const float*)d_in[4];
    const float* temp  = (const float*)d_in[5];
    float* out = (float*)d_out;

    cudaFuncSetAttribute(k1_qkv, cudaFuncAttributeMaxDynamicSharedMemorySize, K1_SMEM);
    cudaFuncSetAttribute(k5_out, cudaFuncAttributeMaxDynamicSharedMemorySize, K5_SMEM);

    k0_zero<<<432, 256>>>(wqkv);
    k_nop1<<<1, 32>>>();     // keep ncu's profiled slot on k1_qkv
    k_nop2<<<1, 32>>>();

    dim3 g1(HW / 64, 1, 16);      // one CTA per n-tile: all 576 m rows, B resident
    k1_qkv<<<g1, 256, K1_SMEM>>>(rgb, ir);

    dim3 g2(2, C3, 16);
    k2_dw<<<g2, 256>>>(wdw);

    dim3 g3(8, NB * HEADS, 2);
    k3_gram<<<g3, 256>>>();

    k4_softmax_M<<<16, 192>>>(wproj, temp);

    dim3 g5(HW / 64, 1, 16);
    k5_out<<<g5, 256, K5_SMEM>>>(out);
}